// round 1
// baseline (speedup 1.0000x reference)
#include <cuda_runtime.h>
#include <math.h>

#define BATCH 16
#define SEQ   1024
#define DIM   768
#define GP    49
#define ROWS  (BATCH * SEQ)      // 16384
#define QKVD  (3 * DIM)          // 2304

// ---------------- scratch (device globals; no allocation allowed) ----------
__device__ float g_qkv[(size_t)ROWS * QKVD];            // 151 MB
__device__ float g_gw [(size_t)ROWS * GP];              // 3.2 MB
__device__ float g_S  [(size_t)BATCH * SEQ * SEQ];      // 67 MB
__device__ float g_rmax[ROWS];
__device__ float g_rsum[ROWS];
__device__ float g_ov [(size_t)ROWS * DIM];             // 50 MB

// ---------------- 128x128x8 SGEMM, 256 threads, 8x8 micro-tile -------------
// C[m,n] = alpha * sum_k A[m,k] * (TB ? B[n,k] : B[k,n])  (+ bias[n])
template<bool TB, bool BIAS>
__global__ void __launch_bounds__(256) sgemm128(
    const float* __restrict__ A, const float* __restrict__ B,
    float* __restrict__ C, const float* __restrict__ bias,
    int K, int lda, int ldb, int ldc,
    long long sA, long long sB, long long sC, float alpha)
{
    __shared__ float As[8][128];
    __shared__ float Bs[8][128];

    const float* Ab = A + (long long)blockIdx.z * sA;
    const float* Bb = B + (long long)blockIdx.z * sB;
    float*       Cb = C + (long long)blockIdx.z * sC;

    const int m0 = blockIdx.y * 128;
    const int n0 = blockIdx.x * 128;
    const int tid = threadIdx.x;
    const int tx = tid & 15;        // 16 column groups
    const int ty = tid >> 4;        // 16 row groups

    // A tile loader: 128 rows x 8 k, float4 per thread
    const int am = tid >> 1;
    const int ak = (tid & 1) << 2;
    // B loaders
    const int bn_t = tid >> 1;          // TB: row of B (n), float4 along k
    const int bk_t = (tid & 1) << 2;
    const int bk_n = tid >> 5;          // NN: k row, float4 along n
    const int bn_n = (tid & 31) << 2;

    float acc[8][8];
#pragma unroll
    for (int i = 0; i < 8; i++)
#pragma unroll
        for (int j = 0; j < 8; j++) acc[i][j] = 0.f;

    for (int k0 = 0; k0 < K; k0 += 8) {
        float4 a4 = *(const float4*)(Ab + (long long)(m0 + am) * lda + k0 + ak);
        As[ak + 0][am] = a4.x; As[ak + 1][am] = a4.y;
        As[ak + 2][am] = a4.z; As[ak + 3][am] = a4.w;
        if (TB) {
            float4 b4 = *(const float4*)(Bb + (long long)(n0 + bn_t) * ldb + k0 + bk_t);
            Bs[bk_t + 0][bn_t] = b4.x; Bs[bk_t + 1][bn_t] = b4.y;
            Bs[bk_t + 2][bn_t] = b4.z; Bs[bk_t + 3][bn_t] = b4.w;
        } else {
            float4 b4 = *(const float4*)(Bb + (long long)(k0 + bk_n) * ldb + n0 + bn_n);
            *(float4*)(&Bs[bk_n][bn_n]) = b4;
        }
        __syncthreads();
#pragma unroll
        for (int kk = 0; kk < 8; kk++) {
            float ra[8], rb[8];
            *(float4*)(ra)     = *(const float4*)(&As[kk][ty * 4]);
            *(float4*)(ra + 4) = *(const float4*)(&As[kk][64 + ty * 4]);
            *(float4*)(rb)     = *(const float4*)(&Bs[kk][tx * 4]);
            *(float4*)(rb + 4) = *(const float4*)(&Bs[kk][64 + tx * 4]);
#pragma unroll
            for (int i = 0; i < 8; i++)
#pragma unroll
                for (int j = 0; j < 8; j++)
                    acc[i][j] = fmaf(ra[i], rb[j], acc[i][j]);
        }
        __syncthreads();
    }

#pragma unroll
    for (int ii = 0; ii < 2; ii++)
#pragma unroll
        for (int i = 0; i < 4; i++) {
            int m = m0 + ii * 64 + ty * 4 + i;
#pragma unroll
            for (int jj = 0; jj < 2; jj++) {
                int n = n0 + jj * 64 + tx * 4;
                float4 r;
                r.x = acc[ii * 4 + i][jj * 4 + 0] * alpha;
                r.y = acc[ii * 4 + i][jj * 4 + 1] * alpha;
                r.z = acc[ii * 4 + i][jj * 4 + 2] * alpha;
                r.w = acc[ii * 4 + i][jj * 4 + 3] * alpha;
                if (BIAS) {
                    r.x += bias[n + 0]; r.y += bias[n + 1];
                    r.z += bias[n + 2]; r.w += bias[n + 3];
                }
                *(float4*)(Cb + (long long)m * ldc + n) = r;
            }
        }
}

// ---------------- gw = softmax(q @ W_gp) per row ----------------------------
__global__ void __launch_bounds__(64) gw_kernel(
    const float* __restrict__ qkv, const float* __restrict__ Wgp,
    float* __restrict__ gw)
{
    __shared__ float qs[DIM];
    __shared__ float lg[GP];
    __shared__ float ssum;
    const int row = blockIdx.x;
    const float* q = qkv + (long long)row * QKVD;
    for (int i = threadIdx.x; i < DIM; i += 64) qs[i] = q[i];
    __syncthreads();
    if (threadIdx.x < GP) {
        float s = 0.f;
        for (int k = 0; k < DIM; k++)
            s = fmaf(qs[k], Wgp[k * GP + threadIdx.x], s);
        lg[threadIdx.x] = s;
    }
    __syncthreads();
    if (threadIdx.x == 0) {
        float m = lg[0];
        for (int j = 1; j < GP; j++) m = fmaxf(m, lg[j]);
        float s = 0.f;
        for (int j = 0; j < GP; j++) { lg[j] = expf(lg[j] - m); s += lg[j]; }
        ssum = s;
    }
    __syncthreads();
    if (threadIdx.x < GP)
        gw[(long long)row * GP + threadIdx.x] = lg[threadIdx.x] / ssum;
}

// ---------------- per-row max & sum(exp) over S ------------------------------
__global__ void __launch_bounds__(256) rowstats_kernel(
    const float* __restrict__ S, float* __restrict__ rmax, float* __restrict__ rsum)
{
    const int row = blockIdx.x;
    const float* s = S + (long long)row * SEQ;
    const int tid = threadIdx.x;
    float v[4];
    float mx = -1e30f;
#pragma unroll
    for (int t = 0; t < 4; t++) { v[t] = s[tid + 256 * t]; mx = fmaxf(mx, v[t]); }
    __shared__ float red[256];
    red[tid] = mx; __syncthreads();
    for (int off = 128; off > 0; off >>= 1) {
        if (tid < off) red[tid] = fmaxf(red[tid], red[tid + off]);
        __syncthreads();
    }
    float m = red[0];
    __syncthreads();
    float sum = 0.f;
#pragma unroll
    for (int t = 0; t < 4; t++) sum += expf(v[t] - m);
    red[tid] = sum; __syncthreads();
    for (int off = 128; off > 0; off >>= 1) {
        if (tid < off) red[tid] += red[tid + off];
        __syncthreads();
    }
    if (tid == 0) { rmax[row] = m; rsum[row] = red[0]; }
}

// ---------------- W = exp(S-m)/sum * (a + (1-a)*<gw_i, gw_m>) in-place -------
__global__ void __launch_bounds__(256) modulate_kernel(
    float* __restrict__ S, const float* __restrict__ gw,
    const float* __restrict__ rmax, const float* __restrict__ rsum,
    const float* __restrict__ alpha_p)
{
    __shared__ float gwm[128][GP + 1];
    const int b  = blockIdx.z;
    const int i0 = blockIdx.y * 64;
    const int m0 = blockIdx.x * 128;
    const int tid = threadIdx.x;

    for (int idx = tid; idx < 128 * GP; idx += 256) {
        int r = idx / GP, c = idx - r * GP;
        gwm[r][c] = gw[(long long)(b * SEQ + m0 + r) * GP + c];
    }
    __syncthreads();

    const float a = 1.f / (1.f + expf(-alpha_p[0]));
    const float oma = 1.f - a;

    const int il = tid >> 2;       // 0..63 row in tile
    const int ms = tid & 3;        // 4 column lanes
    const int grow = b * SEQ + i0 + il;

    float gi[GP];
#pragma unroll
    for (int c = 0; c < GP; c++) gi[c] = gw[(long long)grow * GP + c];

    const float mi  = rmax[grow];
    const float inv = 1.f / rsum[grow];
    float* srow = S + (long long)b * SEQ * SEQ + (long long)(i0 + il) * SEQ + m0;

    for (int mm = 0; mm < 32; mm++) {
        int ml = ms + (mm << 2);
        float dot = 0.f;
#pragma unroll
        for (int c = 0; c < GP; c++) dot = fmaf(gi[c], gwm[ml][c], dot);
        float s = srow[ml];
        srow[ml] = expf(s - mi) * inv * (a + oma * dot);
    }
}

// ---------------- launcher ---------------------------------------------------
extern "C" void kernel_launch(void* const* d_in, const int* in_sizes, int n_in,
                              void* d_out, int out_size)
{
    const float* x      = (const float*)d_in[0];
    const float* W_qkv  = (const float*)d_in[1];
    const float* b_qkv  = (const float*)d_in[2];
    const float* W_proj = (const float*)d_in[3];
    const float* b_proj = (const float*)d_in[4];
    const float* W_gp   = (const float*)d_in[5];
    const float* alpha  = (const float*)d_in[6];
    float* out = (float*)d_out;

    float *qkv, *gw, *S, *rmax, *rsum, *ov;
    cudaGetSymbolAddress((void**)&qkv,  g_qkv);
    cudaGetSymbolAddress((void**)&gw,   g_gw);
    cudaGetSymbolAddress((void**)&S,    g_S);
    cudaGetSymbolAddress((void**)&rmax, g_rmax);
    cudaGetSymbolAddress((void**)&rsum, g_rsum);
    cudaGetSymbolAddress((void**)&ov,   g_ov);

    const float scale = (float)(1.0 / sqrt((double)DIM));

    // 1) qkv = x @ W_qkv + b_qkv      (16384 x 2304 x 768)
    sgemm128<false, true><<<dim3(QKVD / 128, ROWS / 128, 1), 256>>>(
        x, W_qkv, qkv, b_qkv, DIM, DIM, QKVD, QKVD, 0, 0, 0, 1.0f);

    // 2) gw = softmax(q @ W_gp)
    gw_kernel<<<ROWS, 64>>>(qkv, W_gp, gw);

    // 3) S = scale * Q K^T  (batched NT, 16 x 1024x1024x768)
    sgemm128<true, false><<<dim3(SEQ / 128, SEQ / 128, BATCH), 256>>>(
        qkv, qkv + DIM, S, nullptr, DIM, QKVD, QKVD, SEQ,
        (long long)SEQ * QKVD, (long long)SEQ * QKVD, (long long)SEQ * SEQ, scale);

    // 4) row max / sum(exp)
    rowstats_kernel<<<ROWS, 256>>>(S, rmax, rsum);

    // 5) modulate in-place: S <- softmax(S) * (a + (1-a)*group)
    modulate_kernel<<<dim3(SEQ / 128, SEQ / 64, BATCH), 256>>>(S, gw, rmax, rsum, alpha);

    // 6) ov = W @ V  (batched NN, 16 x 1024x768x1024)
    sgemm128<false, false><<<dim3(DIM / 128, SEQ / 128, BATCH), 256>>>(
        S, qkv + 2 * DIM, ov, nullptr, SEQ, SEQ, QKVD, DIM,
        (long long)SEQ * SEQ, (long long)SEQ * QKVD, (long long)SEQ * DIM, 1.0f);

    // 7) out = ov @ W_proj + b_proj   (16384 x 768 x 768)
    sgemm128<false, true><<<dim3(DIM / 128, ROWS / 128, 1), 256>>>(
        ov, W_proj, out, b_proj, DIM, DIM, DIM, DIM, 0, 0, 0, 1.0f);
}

// round 3
// speedup vs baseline: 2.0718x; 2.0718x over previous
#include <cuda_runtime.h>
#include <cuda_fp16.h>
#include <math.h>
#include <stdint.h>

#define BATCH 16
#define SEQ   1024
#define DIM   768
#define GP    49
#define ROWS  (BATCH * SEQ)      // 16384
#define QKVD  (3 * DIM)          // 2304

// ---------------- scratch (device globals; no allocation allowed) ----------
__device__ float g_qkv[(size_t)ROWS * QKVD];
__device__ float g_gw [(size_t)ROWS * GP];
__device__ float g_S  [(size_t)BATCH * SEQ * SEQ];
__device__ float g_rmax[ROWS];
__device__ float g_rsum[ROWS];
__device__ float g_ov [(size_t)ROWS * DIM];
__device__ float g_Wqkvt [(size_t)QKVD * DIM];
__device__ float g_Wprojt[(size_t)DIM * DIM];
__device__ float g_Vt [(size_t)BATCH * DIM * SEQ];

// ================= fp16-split mma.sync GEMM =================================
// C[m,n] = alpha * sum_k A[m,k]*B[n,k] (+ bias[n]);  A,B fp32, K-major rows.
// 128x128 tile, 256 threads, K-chunk 32, double-buffered smem.
#define PAD    40
#define PLANEH (128 * PAD)       // halves per plane
#define STAGEH (4 * PLANEH)      // Ah,Al,Bh,Bl
#define GSMEM  (2 * STAGEH * 2)  // bytes

__device__ __forceinline__ void mma16816(float* d, const uint32_t* a, const uint32_t* b) {
    asm volatile(
        "mma.sync.aligned.m16n8k16.row.col.f32.f16.f16.f32 "
        "{%0,%1,%2,%3},{%4,%5,%6,%7},{%8,%9},{%0,%1,%2,%3};"
        : "+f"(d[0]), "+f"(d[1]), "+f"(d[2]), "+f"(d[3])
        : "r"(a[0]), "r"(a[1]), "r"(a[2]), "r"(a[3]), "r"(b[0]), "r"(b[1]));
}

__device__ __forceinline__ void split_store(half* Hh, half* Hl, int r, int k4, float4 v) {
    half2 h01 = __floats2half2_rn(v.x, v.y);
    half2 h23 = __floats2half2_rn(v.z, v.w);
    half2 l01 = __floats2half2_rn(v.x - __half2float(h01.x), v.y - __half2float(h01.y));
    half2 l23 = __floats2half2_rn(v.z - __half2float(h23.x), v.w - __half2float(h23.y));
    *(half2*)(Hh + r * PAD + k4)     = h01;
    *(half2*)(Hh + r * PAD + k4 + 2) = h23;
    *(half2*)(Hl + r * PAD + k4)     = l01;
    *(half2*)(Hl + r * PAD + k4 + 2) = l23;
}

template<bool BIAS>
__global__ void __launch_bounds__(256, 1) gemm_mma(
    const float* __restrict__ A, int lda, long long strA,
    const float* __restrict__ B, int ldb, long long strB,
    float* __restrict__ C, int ldc, long long strC,
    const float* __restrict__ bias, int K, float alpha)
{
    extern __shared__ __align__(16) half sm[];
    const int tid  = threadIdx.x;
    const int lane = tid & 31;
    const int w    = tid >> 5;
    const int wm   = w & 1;          // 2 warps along M (64 rows each)
    const int wn   = w >> 1;         // 4 warps along N (32 cols each)
    const int m0 = blockIdx.y * 128, n0 = blockIdx.x * 128;
    const float* Ab = A + (long long)blockIdx.z * strA + (long long)m0 * lda;
    const float* Bb = B + (long long)blockIdx.z * strB + (long long)n0 * ldb;
    float*       Cb = C + (long long)blockIdx.z * strC;

    float acc[4][4][4];
#pragma unroll
    for (int i = 0; i < 4; i++)
#pragma unroll
        for (int j = 0; j < 4; j++)
#pragma unroll
            for (int r = 0; r < 4; r++) acc[i][j][r] = 0.f;

    float4 pa[4], pb[4];
    const int nch = K >> 5;

    // prefetch + store chunk 0
#pragma unroll
    for (int i = 0; i < 4; i++) {
        int f = i * 256 + tid, r = f >> 3, k4 = (f & 7) << 2;
        pa[i] = *(const float4*)(Ab + (long long)r * lda + k4);
        pb[i] = *(const float4*)(Bb + (long long)r * ldb + k4);
    }
    {
        half* Ah = sm;             half* Al = Ah + PLANEH;
        half* Bh = Al + PLANEH;    half* Bl = Bh + PLANEH;
#pragma unroll
        for (int i = 0; i < 4; i++) {
            int f = i * 256 + tid, r = f >> 3, k4 = (f & 7) << 2;
            split_store(Ah, Al, r, k4, pa[i]);
            split_store(Bh, Bl, r, k4, pb[i]);
        }
    }
    __syncthreads();

    for (int c = 0; c < nch; ++c) {
        const int st = c & 1;
        if (c + 1 < nch) {
            const int k0 = (c + 1) << 5;
#pragma unroll
            for (int i = 0; i < 4; i++) {
                int f = i * 256 + tid, r = f >> 3, k4 = (f & 7) << 2;
                pa[i] = *(const float4*)(Ab + (long long)r * lda + k0 + k4);
                pb[i] = *(const float4*)(Bb + (long long)r * ldb + k0 + k4);
            }
        }
        const half* Ah = sm + st * STAGEH;
        const half* Al = Ah + PLANEH;
        const half* Bh = Al + PLANEH;
        const half* Bl = Bh + PLANEH;
#pragma unroll
        for (int ks = 0; ks < 2; ks++) {
            const int kb = ks * 16 + ((lane & 3) << 1);
            uint32_t ah[4][4], al[4][4], bh[4][2], bl[4][2];
#pragma unroll
            for (int mi = 0; mi < 4; mi++) {
                int rb = wm * 64 + mi * 16 + (lane >> 2);
                ah[mi][0] = *(const uint32_t*)(Ah + rb * PAD + kb);
                ah[mi][1] = *(const uint32_t*)(Ah + (rb + 8) * PAD + kb);
                ah[mi][2] = *(const uint32_t*)(Ah + rb * PAD + kb + 8);
                ah[mi][3] = *(const uint32_t*)(Ah + (rb + 8) * PAD + kb + 8);
            }
#pragma unroll
            for (int ni = 0; ni < 4; ni++) {
                int nb = wn * 32 + ni * 8 + (lane >> 2);
                bh[ni][0] = *(const uint32_t*)(Bh + nb * PAD + kb);
                bh[ni][1] = *(const uint32_t*)(Bh + nb * PAD + kb + 8);
            }
#pragma unroll
            for (int mi = 0; mi < 4; mi++)
#pragma unroll
                for (int ni = 0; ni < 4; ni++)
                    mma16816(acc[mi][ni], ah[mi], bh[ni]);
#pragma unroll
            for (int mi = 0; mi < 4; mi++) {
                int rb = wm * 64 + mi * 16 + (lane >> 2);
                al[mi][0] = *(const uint32_t*)(Al + rb * PAD + kb);
                al[mi][1] = *(const uint32_t*)(Al + (rb + 8) * PAD + kb);
                al[mi][2] = *(const uint32_t*)(Al + rb * PAD + kb + 8);
                al[mi][3] = *(const uint32_t*)(Al + (rb + 8) * PAD + kb + 8);
            }
#pragma unroll
            for (int mi = 0; mi < 4; mi++)
#pragma unroll
                for (int ni = 0; ni < 4; ni++)
                    mma16816(acc[mi][ni], al[mi], bh[ni]);
#pragma unroll
            for (int ni = 0; ni < 4; ni++) {
                int nb = wn * 32 + ni * 8 + (lane >> 2);
                bl[ni][0] = *(const uint32_t*)(Bl + nb * PAD + kb);
                bl[ni][1] = *(const uint32_t*)(Bl + nb * PAD + kb + 8);
            }
#pragma unroll
            for (int mi = 0; mi < 4; mi++)
#pragma unroll
                for (int ni = 0; ni < 4; ni++)
                    mma16816(acc[mi][ni], ah[mi], bl[ni]);
        }
        __syncthreads();
        if (c + 1 < nch) {
            half* nAh = sm + (st ^ 1) * STAGEH;
            half* nAl = nAh + PLANEH;
            half* nBh = nAl + PLANEH;
            half* nBl = nBh + PLANEH;
#pragma unroll
            for (int i = 0; i < 4; i++) {
                int f = i * 256 + tid, r = f >> 3, k4 = (f & 7) << 2;
                split_store(nAh, nAl, r, k4, pa[i]);
                split_store(nBh, nBl, r, k4, pb[i]);
            }
        }
        __syncthreads();
    }

    // epilogue: direct float2 stores
    const int r0 = m0 + wm * 64 + (lane >> 2);
    const int c0 = n0 + wn * 32 + ((lane & 3) << 1);
#pragma unroll
    for (int mi = 0; mi < 4; mi++) {
        int rr = r0 + mi * 16;
#pragma unroll
        for (int ni = 0; ni < 4; ni++) {
            int cc = c0 + ni * 8;
            float bx = 0.f, by = 0.f;
            if (BIAS) { bx = bias[cc]; by = bias[cc + 1]; }
            float2 v0 = make_float2(acc[mi][ni][0] * alpha + bx,
                                    acc[mi][ni][1] * alpha + by);
            float2 v1 = make_float2(acc[mi][ni][2] * alpha + bx,
                                    acc[mi][ni][3] * alpha + by);
            *(float2*)(Cb + (long long)rr * ldc + cc)       = v0;
            *(float2*)(Cb + (long long)(rr + 8) * ldc + cc) = v1;
        }
    }
}

// ======================= fp32 transpose (32x32 tiles) =======================
__global__ void __launch_bounds__(256) transpose_f32(
    const float* __restrict__ in, float* __restrict__ out,
    int ldin, int ldout, long long sIn, long long sOut)
{
    __shared__ float t[32][33];
    const float* ib = in + (long long)blockIdx.z * sIn;
    float* ob = out + (long long)blockIdx.z * sOut;
    int r0 = blockIdx.y * 32, c0 = blockIdx.x * 32;
    int x = threadIdx.x & 31, y = threadIdx.x >> 5;
#pragma unroll
    for (int j = 0; j < 32; j += 8)
        t[y + j][x] = ib[(long long)(r0 + y + j) * ldin + c0 + x];
    __syncthreads();
#pragma unroll
    for (int j = 0; j < 32; j += 8)
        ob[(long long)(c0 + y + j) * ldout + r0 + x] = t[x][y + j];
}

// ---------------- gw = softmax(q @ W_gp) per row ----------------------------
__global__ void __launch_bounds__(64) gw_kernel(
    const float* __restrict__ qkv, const float* __restrict__ Wgp,
    float* __restrict__ gw)
{
    __shared__ float qs[DIM];
    __shared__ float lg[GP];
    __shared__ float ssum;
    const int row = blockIdx.x;
    const float* q = qkv + (long long)row * QKVD;
    for (int i = threadIdx.x; i < DIM; i += 64) qs[i] = q[i];
    __syncthreads();
    if (threadIdx.x < GP) {
        float s = 0.f;
        for (int k = 0; k < DIM; k++)
            s = fmaf(qs[k], Wgp[k * GP + threadIdx.x], s);
        lg[threadIdx.x] = s;
    }
    __syncthreads();
    if (threadIdx.x == 0) {
        float m = lg[0];
        for (int j = 1; j < GP; j++) m = fmaxf(m, lg[j]);
        float s = 0.f;
        for (int j = 0; j < GP; j++) { lg[j] = expf(lg[j] - m); s += lg[j]; }
        ssum = s;
    }
    __syncthreads();
    if (threadIdx.x < GP)
        gw[(long long)row * GP + threadIdx.x] = lg[threadIdx.x] / ssum;
}

// ---------------- per-row max & sum(exp) over S ------------------------------
__global__ void __launch_bounds__(256) rowstats_kernel(
    const float* __restrict__ S, float* __restrict__ rmax, float* __restrict__ rsum)
{
    const int row = blockIdx.x;
    const float* s = S + (long long)row * SEQ;
    const int tid = threadIdx.x;
    float v[4];
    float mx = -1e30f;
#pragma unroll
    for (int t = 0; t < 4; t++) { v[t] = s[tid + 256 * t]; mx = fmaxf(mx, v[t]); }
    __shared__ float red[256];
    red[tid] = mx; __syncthreads();
    for (int off = 128; off > 0; off >>= 1) {
        if (tid < off) red[tid] = fmaxf(red[tid], red[tid + off]);
        __syncthreads();
    }
    float m = red[0];
    __syncthreads();
    float sum = 0.f;
#pragma unroll
    for (int t = 0; t < 4; t++) sum += expf(v[t] - m);
    red[tid] = sum; __syncthreads();
    for (int off = 128; off > 0; off >>= 1) {
        if (tid < off) red[tid] += red[tid + off];
        __syncthreads();
    }
    if (tid == 0) { rmax[row] = m; rsum[row] = red[0]; }
}

// ---------------- W = exp(S-m)/sum * (a + (1-a)*<gw_i, gw_m>) in-place -------
__global__ void __launch_bounds__(256) modulate_kernel(
    float* __restrict__ S, const float* __restrict__ gw,
    const float* __restrict__ rmax, const float* __restrict__ rsum,
    const float* __restrict__ alpha_p)
{
    __shared__ float gwm[128][GP + 1];
    const int b  = blockIdx.z;
    const int i0 = blockIdx.y * 64;
    const int m0 = blockIdx.x * 128;
    const int tid = threadIdx.x;

    for (int idx = tid; idx < 128 * GP; idx += 256) {
        int r = idx / GP, c = idx - r * GP;
        gwm[r][c] = gw[(long long)(b * SEQ + m0 + r) * GP + c];
    }
    __syncthreads();

    const float a = 1.f / (1.f + expf(-alpha_p[0]));
    const float oma = 1.f - a;

    const int il = tid >> 2;
    const int ms = tid & 3;
    const int grow = b * SEQ + i0 + il;

    float gi[GP];
#pragma unroll
    for (int c = 0; c < GP; c++) gi[c] = gw[(long long)grow * GP + c];

    const float mi  = rmax[grow];
    const float inv = 1.f / rsum[grow];
    float* srow = S + (long long)b * SEQ * SEQ + (long long)(i0 + il) * SEQ + m0;

    for (int mm = 0; mm < 32; mm++) {
        int ml = ms + (mm << 2);
        float dot = 0.f;
#pragma unroll
        for (int c = 0; c < GP; c++) dot = fmaf(gi[c], gwm[ml][c], dot);
        float s = srow[ml];
        srow[ml] = expf(s - mi) * inv * (a + oma * dot);
    }
}

// ---------------- launcher ---------------------------------------------------
extern "C" void kernel_launch(void* const* d_in, const int* in_sizes, int n_in,
                              void* d_out, int out_size)
{
    const float* x      = (const float*)d_in[0];
    const float* W_qkv  = (const float*)d_in[1];
    const float* b_qkv  = (const float*)d_in[2];
    const float* W_proj = (const float*)d_in[3];
    const float* b_proj = (const float*)d_in[4];
    const float* W_gp   = (const float*)d_in[5];
    const float* alpha  = (const float*)d_in[6];
    float* out = (float*)d_out;

    float *qkv, *gw, *S, *rmax, *rsum, *ov, *Wqkvt, *Wprojt, *Vt;
    cudaGetSymbolAddress((void**)&qkv,    g_qkv);
    cudaGetSymbolAddress((void**)&gw,     g_gw);
    cudaGetSymbolAddress((void**)&S,      g_S);
    cudaGetSymbolAddress((void**)&rmax,   g_rmax);
    cudaGetSymbolAddress((void**)&rsum,   g_rsum);
    cudaGetSymbolAddress((void**)&ov,     g_ov);
    cudaGetSymbolAddress((void**)&Wqkvt,  g_Wqkvt);
    cudaGetSymbolAddress((void**)&Wprojt, g_Wprojt);
    cudaGetSymbolAddress((void**)&Vt,     g_Vt);

    const float scale = (float)(1.0 / sqrt((double)DIM));
    cudaFuncSetAttribute(gemm_mma<true>,  cudaFuncAttributeMaxDynamicSharedMemorySize, GSMEM);
    cudaFuncSetAttribute(gemm_mma<false>, cudaFuncAttributeMaxDynamicSharedMemorySize, GSMEM);

    // weight transposes (B operands must be K-major rows)
    transpose_f32<<<dim3(QKVD / 32, DIM / 32, 1), 256>>>(W_qkv, Wqkvt, QKVD, DIM, 0, 0);
    transpose_f32<<<dim3(DIM / 32, DIM / 32, 1), 256>>>(W_proj, Wprojt, DIM, DIM, 0, 0);

    // 1) qkv = x @ W_qkv + b_qkv     M=16384 N=2304 K=768
    gemm_mma<true><<<dim3(QKVD / 128, ROWS / 128, 1), 256, GSMEM>>>(
        x, DIM, 0, Wqkvt, DIM, 0, qkv, QKVD, 0, b_qkv, DIM, 1.0f);

    // 2) gw = softmax(q @ W_gp)
    gw_kernel<<<ROWS, 64>>>(qkv, W_gp, gw);

    // V^T per batch
    transpose_f32<<<dim3(DIM / 32, SEQ / 32, BATCH), 256>>>(
        qkv + 2 * DIM, Vt, QKVD, SEQ, (long long)SEQ * QKVD, (long long)DIM * SEQ);

    // 3) S = scale * Q K^T           batched M=N=1024 K=768
    gemm_mma<false><<<dim3(SEQ / 128, SEQ / 128, BATCH), 256, GSMEM>>>(
        qkv, QKVD, (long long)SEQ * QKVD,
        qkv + DIM, QKVD, (long long)SEQ * QKVD,
        S, SEQ, (long long)SEQ * SEQ, nullptr, DIM, scale);

    // 4) row max / sum(exp)
    rowstats_kernel<<<ROWS, 256>>>(S, rmax, rsum);

    // 5) modulate in-place
    modulate_kernel<<<dim3(SEQ / 128, SEQ / 64, BATCH), 256>>>(S, gw, rmax, rsum, alpha);

    // 6) ov = W @ V                  batched M=1024 N=768 K=1024
    gemm_mma<false><<<dim3(DIM / 128, SEQ / 128, BATCH), 256, GSMEM>>>(
        S, SEQ, (long long)SEQ * SEQ,
        Vt, SEQ, (long long)DIM * SEQ,
        ov, DIM, (long long)SEQ * DIM, nullptr, SEQ, 1.0f);

    // 7) out = ov @ W_proj + b_proj  M=16384 N=768 K=768
    gemm_mma<true><<<dim3(DIM / 128, ROWS / 128, 1), 256, GSMEM>>>(
        ov, DIM, 0, Wprojt, DIM, 0, out, DIM, 0, b_proj, DIM, 1.0f);
}